// round 15
// baseline (speedup 1.0000x reference)
#include <cuda_runtime.h>
#include <cuda_bf16.h>
#include <cstdint>

// SpanGenerator: out = concat_{L=1..8} [ sliding sums of length L starting at
// token index 1 ] over input [B=8, S=512, D=768] fp32.
// span(L, i) = sum_{k=1+i}^{L+i} x[b, k, :],  valid for 0 <= i <= S-1-L.
//
// Per block: 8 span-indices, one per iteration. Each iteration computes the 8
// running-sum rows (one per span length) into a 24 KB SMEM buffer and drains
// it with per-L cp.async.bulk (1-D TMA) copies. Double-buffered; wait_group 1
// keeps the previous drain in flight. 48 KB smem/block -> 4 CTAs/SM for
// 4 concurrent drain pipelines per SM.

#define BB 8
#define SS 512
#define DD 768
#define D4 (DD / 4)          // 192 float4 lanes
#define NROWS 4060           // sum_{L=1..8} (512 - L)
#define ROWB (DD * 4)        // 3072 bytes per output row

#define ITERS 8              // span-indices per block (1 per iteration)
#define BUF_ROWS 8           // one row per span length L
#define BUF_F4 (BUF_ROWS * D4)
#define SMEM_BYTES (2 * BUF_ROWS * ROWB)   // 48 KB (two 24 KB buffers)

__global__ __launch_bounds__(D4, 4)
void span_kernel(const float4* __restrict__ in, float4* __restrict__ out) {
    extern __shared__ float4 sm[];       // [2][8 L][D4]

    const int d  = threadIdx.x;          // 0..191 (float4 index in D)
    const int b  = blockIdx.y;           // batch
    const int i0 = blockIdx.x * ITERS;   // first span-index of this block

    const float4* src = in + (size_t)b * SS * D4 + d;
    const int OFF[8] = {0, 511, 1021, 1530, 2038, 2545, 3051, 3556};

    // Sliding window w[k] = x[b, 1 + i + k, dquad]. Prologue fills w[0..6];
    // clamped rows only feed outputs that are never drained.
    float4 w[8];
#pragma unroll
    for (int k = 0; k < 7; k++) {
        int s = 1 + i0 + k;
        s = (s < SS - 1) ? s : (SS - 1);
        w[k] = src[(size_t)s * D4];
    }

    int p = 0;
#pragma unroll
    for (int it = 0; it < ITERS; it++) {
        const int i = i0 + it;

        // Last window slot: x[b, i+8, :] (clamped, branch-free).
        {
            int s = i + 8;
            s = (s < SS - 1) ? s : (SS - 1);
            w[7] = src[(size_t)s * D4];
        }

        float4* buf = sm + p * BUF_F4;
        float4 acc = make_float4(0.f, 0.f, 0.f, 0.f);
#pragma unroll
        for (int L = 0; L < 8; L++) {
            acc.x += w[L].x;
            acc.y += w[L].y;
            acc.z += w[L].z;
            acc.w += w[L].w;
            buf[(size_t)L * D4 + d] = acc;
        }

        __syncthreads();
        asm volatile("fence.proxy.async.shared::cta;" ::: "memory");

        if (threadIdx.x < 8) {
            const int L = threadIdx.x;               // span length L+1
            if (i + L + 1 < SS) {                    // row (L, i) is valid
                float4* dst = out + ((size_t)b * NROWS + OFF[L] + i) * D4;
                uint32_t saddr = (uint32_t)__cvta_generic_to_shared(
                    buf + (size_t)L * D4);
                asm volatile(
                    "cp.async.bulk.global.shared::cta.bulk_group [%0], [%1], %2;"
                    :: "l"(dst), "r"(saddr), "n"(ROWB) : "memory");
            }
            asm volatile("cp.async.bulk.commit_group;" ::: "memory");
            // Ensure the OTHER buffer's drain (committed last iteration) is
            // done before it gets overwritten next iteration.
            asm volatile("cp.async.bulk.wait_group 1;" ::: "memory");
        }
        __syncthreads();

        // Slide the window by 1.
#pragma unroll
        for (int k = 0; k < 7; k++) w[k] = w[k + 1];
        p ^= 1;
    }

    // Final drain: only the last buffer's copies remain outstanding.
    if (threadIdx.x < 8) {
        asm volatile("cp.async.bulk.wait_group 0;" ::: "memory");
    }
}

extern "C" void kernel_launch(void* const* d_in, const int* in_sizes, int n_in,
                              void* d_out, int out_size) {
    const float4* in  = (const float4*)d_in[0];   // tensor [8, 512, 768] fp32
    float4*       out = (float4*)d_out;           // [8, 4060, 768] fp32
    (void)in_sizes; (void)n_in; (void)out_size;   // max_span_length fixed at 8

    cudaFuncSetAttribute(span_kernel,
                         cudaFuncAttributeMaxDynamicSharedMemorySize, SMEM_BYTES);

    dim3 grid((SS - 1 + ITERS - 1) / ITERS, BB);    // (64, 8)
    dim3 block(D4);                                  // 192 threads
    span_kernel<<<grid, block, SMEM_BYTES>>>(in, out);
}